// round 10
// baseline (speedup 1.0000x reference)
#include <cuda_runtime.h>
#include <cstdint>

// AdditiveAttention: B=2, L=512, S=512, H=8, E=32, D=64 (fp32)
// Warp-specialized: warps 0-7 produce p=exp(score) per 64-s chunk (MUFU+FMA),
// warps 8-15 consume p*V into register accumulators (FMA+LDS). 2-stage ring,
// named-barrier producer/consumer handshake. p stored as duplicated (p,p) u64.

namespace {
constexpr int B = 2, L = 512, S = 512, H = 8, E = 32, D = 64;
constexpr int TL = 64;
constexpr int THREADS = 512;
constexpr int KS_STRIDE = 36;     // floats per key row (conflict-free)
constexpr int PR_STRIDE = 66;     // u64 pairs per p row (conflict-free reads)
constexpr int VS_STRIDE = 68;     // floats per V row
constexpr int CHUNK = 64;
constexpr int NCHUNK = S / CHUNK; // 8
constexpr int KS_FLOATS = S * KS_STRIDE;            // 18432
constexpr int PR_FLOATS = 2 * TL * PR_STRIDE * 2;   // 16896
constexpr int VB_FLOATS = 2 * CHUNK * VS_STRIDE;    // 8704
constexpr int SMEM_FLOATS = KS_FLOATS + PR_FLOATS + VB_FLOATS + TL;
constexpr int SMEM_BYTES = SMEM_FLOATS * (int)sizeof(float);  // ~176.4KB
constexpr float TWO_LOG2E = 2.885390081777927f;
constexpr float LOG2E = 1.4426950408889634f;
}

using u64 = unsigned long long;

__device__ __forceinline__ float ex2f(float x) {
    float y; asm("ex2.approx.f32 %0, %1;" : "=f"(y) : "f"(x)); return y;
}
__device__ __forceinline__ float rcpf(float x) {
    float y; asm("rcp.approx.f32 %0, %1;" : "=f"(y) : "f"(x)); return y;
}
__device__ __forceinline__ u64 pk(float a, float b) {
    u64 d; asm("mov.b64 %0, {%1, %2};" : "=l"(d) : "f"(a), "f"(b)); return d;
}
__device__ __forceinline__ void upk(u64 d, float& a, float& b) {
    asm("mov.b64 {%0, %1}, %2;" : "=f"(a), "=f"(b) : "l"(d));
}
__device__ __forceinline__ u64 fma2(u64 a, u64 b, u64 c) {
    u64 d; asm("fma.rn.f32x2 %0, %1, %2, %3;" : "=l"(d) : "l"(a), "l"(b), "l"(c)); return d;
}
__device__ __forceinline__ void bar_sync(int id, int cnt) {
    asm volatile("bar.sync %0, %1;" :: "r"(id), "r"(cnt) : "memory");
}
__device__ __forceinline__ void bar_arrive(int id, int cnt) {
    asm volatile("bar.arrive %0, %1;" :: "r"(id), "r"(cnt) : "memory");
}
__device__ __forceinline__ void membar_cta() {
    asm volatile("membar.cta;" ::: "memory");
}

__global__ void __launch_bounds__(THREADS, 1)
addattn_kernel(const float* __restrict__ q, const float* __restrict__ k,
               const float* __restrict__ vals, const float* __restrict__ vvec,
               const float* __restrict__ mask, const float* __restrict__ klen,
               float* __restrict__ out)
{
    extern __shared__ float sm[];
    float* ks   = sm;                       // [S][KS_STRIDE] exp2(c*k)
    u64*   prng = reinterpret_cast<u64*>(sm + KS_FLOATS); // [2][TL][PR_STRIDE] (p,p)
    float* vbuf = sm + KS_FLOATS + PR_FLOATS;             // [2][CHUNK][VS_STRIDE]
    float* rsum = vbuf + VB_FLOATS;                       // [TL]

    const int tid = threadIdx.x;
    const int bid = blockIdx.x;
    const int lb = bid & 7;
    const int h  = (bid >> 3) & 7;
    const int b  = bid >> 6;
    const int l0 = lb * TL;

    // ---- all threads: stage keys as Ek = exp2(c*k) ----
    for (int i = tid; i < S * (E / 4); i += THREADS) {
        int s = i >> 3, e4 = i & 7;
        float4 t = reinterpret_cast<const float4*>(
            k + ((size_t)((b * S + s) * H + h)) * E)[e4];
        t.x = ex2f(TWO_LOG2E * t.x); t.y = ex2f(TWO_LOG2E * t.y);
        t.z = ex2f(TWO_LOG2E * t.z); t.w = ex2f(TWO_LOG2E * t.w);
        *reinterpret_cast<float4*>(ks + s * KS_STRIDE + e4 * 4) = t;
    }
    __syncthreads();

    const u64 ONES2 = pk(1.f, 1.f);

    if (tid < 256) {
        // ================= PRODUCER (warps 0-7) =================
        const int wid  = tid >> 5;
        const int lane = tid & 31;
        const int row  = wid * 8 + (lane >> 2);   // 0..63
        const int sof  = lane & 3;

        // q row -> packed Eq; v constants: 3 quad groups + 5 packed-simple
        u64 qp01[8], qp23[8];
        float v0c[3], v1c[3], v2c[3], v3c[3];
        u64 vp01s[5], vp23s[5];
        float vsumtot = 0.f;
        {
            const float4* qg = reinterpret_cast<const float4*>(
                q + ((size_t)((b * L + l0 + row) * H + h)) * E);
            const float4* vg = reinterpret_cast<const float4*>(vvec);
#pragma unroll
            for (int e4 = 0; e4 < 8; ++e4) {
                float4 t = qg[e4];
                qp01[e4] = pk(ex2f(t.x * TWO_LOG2E), ex2f(t.y * TWO_LOG2E));
                qp23[e4] = pk(ex2f(t.z * TWO_LOG2E), ex2f(t.w * TWO_LOG2E));
                float4 u = vg[e4];
                vsumtot += (u.x + u.y) + (u.z + u.w);
                if (e4 < 3) {
                    v0c[e4] = u.x; v1c[e4] = u.y; v2c[e4] = u.z; v3c[e4] = u.w;
                } else {
                    vp01s[e4 - 3] = pk(u.x, u.y);
                    vp23s[e4 - 3] = pk(u.z, u.w);
                }
            }
        }
        const float baseL = vsumtot * LOG2E;
        const float* maskrow = mask + (size_t)(l0 + row) * S;
        const float* klrow   = klen + (size_t)b * S;
        float psum = 0.f;

        for (int c = 0; c < NCHUNK; ++c) {
            const int st = c & 1;
            if (c >= 2) bar_sync(3 + st, 512);       // wait stage empty
            u64* prs = prng + (st * TL + row) * PR_STRIDE;
            const float* ksc = ks + (c * CHUNK) * KS_STRIDE;
#pragma unroll 2
            for (int jj = 0; jj < 16; ++jj) {
                const int sl = 4 * jj + sof;
                const ulonglong2* kr =
                    reinterpret_cast<const ulonglong2*>(ksc + sl * KS_STRIDE);
                float accP0 = 0.f, accP1 = 0.f;
                u64 accV = pk(0.f, 0.f);
#pragma unroll
                for (int g = 0; g < 3; ++g) {        // quad: 1 rcp / 4 elems
                    ulonglong2 kk2 = kr[g];
                    u64 A2 = fma2(qp01[g], kk2.x, ONES2);
                    u64 B2 = fma2(qp23[g], kk2.y, ONES2);
                    float A0, A1, B0, B1; upk(A2, A0, A1); upk(B2, B0, B1);
                    float denA = A0 * A1;
                    float denB = B0 * B1;
                    float numA = fmaf(v0c[g], A1, v1c[g] * A0);
                    float numB = fmaf(v2c[g], B1, v3c[g] * B0);
                    float num = fmaf(numA, denB, numB * denA);
                    float den = denA * denB;
                    if (g & 1) accP1 = fmaf(num, rcpf(den), accP1);
                    else       accP0 = fmaf(num, rcpf(den), accP0);
                }
#pragma unroll
                for (int g = 3; g < 8; ++g) {        // packed-simple
                    ulonglong2 kk2 = kr[g];
                    u64 d01 = fma2(qp01[g], kk2.x, ONES2);
                    u64 d23 = fma2(qp23[g], kk2.y, ONES2);
                    float a0, a1, a2, a3; upk(d01, a0, a1); upk(d23, a2, a3);
                    u64 r01 = pk(rcpf(a0), rcpf(a1));
                    u64 r23 = pk(rcpf(a2), rcpf(a3));
                    accV = fma2(vp01s[g - 3], r01, accV);
                    accV = fma2(vp23s[g - 3], r23, accV);
                }
                float vlo, vhi; upk(accV, vlo, vhi);
                float a = (accP0 + accP1) + (vlo + vhi);
                const int sg = c * CHUNK + sl;
                float mk = maskrow[sg] + klrow[sg];
                float p = ex2f(fmaf(-2.f * LOG2E, a, fmaf(LOG2E, mk, baseL)));
                psum += p;
                prs[sl] = pk(p, p);
            }
            if (c == NCHUNK - 1) {
                psum += __shfl_xor_sync(0xffffffffu, psum, 1);
                psum += __shfl_xor_sync(0xffffffffu, psum, 2);
                if (sof == 0) rsum[row] = rcpf(psum);
            }
            membar_cta();
            bar_arrive(1 + st, 512);                 // signal stage full
        }
    } else {
        // ================= CONSUMER (warps 8-15) =================
        const int ci = tid - 256;                    // 0..255
        const int r2 = ci >> 3;                      // 0..31 -> rows 2r2, 2r2+1
        const int d8 = (ci & 7) * 8;                 // d slice [d8, d8+8)

        u64 acc0[4], acc1[4];
#pragma unroll
        for (int m = 0; m < 4; ++m) { acc0[m] = pk(0.f, 0.f); acc1[m] = pk(0.f, 0.f); }

        for (int c = 0; c < NCHUNK; ++c) {
            const int st = c & 1;
            float* vch = vbuf + st * CHUNK * VS_STRIDE;
            // stage V chunk (consumer-collective)
            for (int t = ci; t < CHUNK * (D / 4); t += 256) {
                int ss = t >> 4, d4 = t & 15;
                float4 ld = reinterpret_cast<const float4*>(
                    vals + ((size_t)((b * S + c * CHUNK + ss) * H + h)) * D)[d4];
                *reinterpret_cast<float4*>(vch + ss * VS_STRIDE + d4 * 4) = ld;
            }
            bar_sync(5, 256);                        // V visible to all consumers
            bar_sync(1 + st, 512);                   // wait p full

            const u64* p0p = prng + (st * TL + 2 * r2) * PR_STRIDE;
            const u64* p1p = p0p + PR_STRIDE;
#pragma unroll 2
            for (int jb = 0; jb < 16; ++jb) {
                ulonglong2 p0a = reinterpret_cast<const ulonglong2*>(p0p + 4 * jb)[0];
                ulonglong2 p0b = reinterpret_cast<const ulonglong2*>(p0p + 4 * jb)[1];
                ulonglong2 p1a = reinterpret_cast<const ulonglong2*>(p1p + 4 * jb)[0];
                ulonglong2 p1b = reinterpret_cast<const ulonglong2*>(p1p + 4 * jb)[1];
                u64 P0[4] = {p0a.x, p0a.y, p0b.x, p0b.y};
                u64 P1[4] = {p1a.x, p1a.y, p1b.x, p1b.y};
#pragma unroll
                for (int s2 = 0; s2 < 4; ++s2) {
                    const float* vr = vch + (4 * jb + s2) * VS_STRIDE + d8;
                    ulonglong2 va  = reinterpret_cast<const ulonglong2*>(vr)[0];
                    ulonglong2 vb2 = reinterpret_cast<const ulonglong2*>(vr)[1];
                    acc0[0] = fma2(va.x,  P0[s2], acc0[0]);
                    acc0[1] = fma2(va.y,  P0[s2], acc0[1]);
                    acc0[2] = fma2(vb2.x, P0[s2], acc0[2]);
                    acc0[3] = fma2(vb2.y, P0[s2], acc0[3]);
                    acc1[0] = fma2(va.x,  P1[s2], acc1[0]);
                    acc1[1] = fma2(va.y,  P1[s2], acc1[1]);
                    acc1[2] = fma2(vb2.x, P1[s2], acc1[2]);
                    acc1[3] = fma2(vb2.y, P1[s2], acc1[3]);
                }
            }
            bar_arrive(3 + st, 512);                 // signal stage empty
        }

        // normalize + store (rsum visible: written before last FULL arrive)
#pragma unroll
        for (int r = 0; r < 2; ++r) {
            const u64* acc = r ? acc1 : acc0;
            int rowg = 2 * r2 + r;
            float rn = rsum[rowg];
            float* og = out + ((size_t)((b * L + l0 + rowg) * H + h)) * D + d8;
            float o0, o1, o2, o3, o4, o5, o6, o7;
            upk(acc[0], o0, o1); upk(acc[1], o2, o3);
            upk(acc[2], o4, o5); upk(acc[3], o6, o7);
            *reinterpret_cast<float4*>(og) =
                make_float4(o0 * rn, o1 * rn, o2 * rn, o3 * rn);
            *reinterpret_cast<float4*>(og + 4) =
                make_float4(o4 * rn, o5 * rn, o6 * rn, o7 * rn);
        }
    }
}

extern "C" void kernel_launch(void* const* d_in, const int* in_sizes, int n_in,
                              void* d_out, int out_size)
{
    (void)in_sizes; (void)n_in; (void)out_size;
    cudaFuncSetAttribute(addattn_kernel,
                         cudaFuncAttributeMaxDynamicSharedMemorySize, SMEM_BYTES);
    const float* q    = (const float*)d_in[0];
    const float* k    = (const float*)d_in[1];
    const float* vals = (const float*)d_in[2];
    const float* vvec = (const float*)d_in[3];
    const float* mask = (const float*)d_in[4];
    const float* klen = (const float*)d_in[5];
    addattn_kernel<<<B * H * (L / TL), THREADS, SMEM_BYTES>>>(
        q, k, vals, vvec, mask, klen, (float*)d_out);
}

// round 11
// speedup vs baseline: 1.0594x; 1.0594x over previous
#include <cuda_runtime.h>
#include <cstdint>

// AdditiveAttention: B=2, L=512, S=512, H=8, E=32, D=64 (fp32)
// 1024 threads (8 warps/SMSP). Split-E: thread (l, eh, sof) computes half the
// e-groups for s=8j+sof; halves combined via shfl_xor(8). Finalize (exp/store)
// alternates by j parity. Quad/simple mix alternates per j to balance FMA/MUFU.
// Phase3: 2x8 register tiles, 4 s-subgroups, smem partial reduce.

namespace {
constexpr int B = 2, L = 512, S = 512, H = 8, E = 32, D = 64;
constexpr int TL = 64;
constexpr int THREADS = 1024;
constexpr int SC_STRIDE = 524;
constexpr int KS_STRIDE = 36;
constexpr int VS_STRIDE = 68;
constexpr int PB_STRIDE = 68;
constexpr int SMEM_FLOATS = TL * SC_STRIDE + S * KS_STRIDE + TL * VS_STRIDE + TL;
constexpr int SMEM_BYTES = SMEM_FLOATS * (int)sizeof(float);   // ~225.7KB
constexpr float TWO_LOG2E = 2.885390081777927f;
constexpr float LOG2E = 1.4426950408889634f;
}

using u64 = unsigned long long;

__device__ __forceinline__ float ex2f(float x) {
    float y; asm("ex2.approx.f32 %0, %1;" : "=f"(y) : "f"(x)); return y;
}
__device__ __forceinline__ float rcpf(float x) {
    float y; asm("rcp.approx.f32 %0, %1;" : "=f"(y) : "f"(x)); return y;
}
__device__ __forceinline__ u64 pk(float a, float b) {
    u64 d; asm("mov.b64 %0, {%1, %2};" : "=l"(d) : "f"(a), "f"(b)); return d;
}
__device__ __forceinline__ void upk(u64 d, float& a, float& b) {
    asm("mov.b64 {%0, %1}, %2;" : "=f"(a), "=f"(b) : "l"(d));
}
__device__ __forceinline__ u64 fma2(u64 a, u64 b, u64 c) {
    u64 d; asm("fma.rn.f32x2 %0, %1, %2, %3;" : "=l"(d) : "l"(a), "l"(b), "l"(c)); return d;
}

__global__ void __launch_bounds__(THREADS, 1)
addattn_kernel(const float* __restrict__ q, const float* __restrict__ k,
               const float* __restrict__ vals, const float* __restrict__ vvec,
               const float* __restrict__ mask, const float* __restrict__ klen,
               float* __restrict__ out)
{
    extern __shared__ float sm[];
    float* sc   = sm;                     // [TL][SC_STRIDE] unnormalized probs
    float* ks   = sc + TL * SC_STRIDE;    // [S][KS_STRIDE] Ek; reused as pbuf
    float* vs   = ks + S * KS_STRIDE;     // [TL][VS_STRIDE] values chunk
    float* rsum = vs + TL * VS_STRIDE;    // [TL] 1/rowsum

    const int tid = threadIdx.x;
    const int bid = blockIdx.x;
    const int lb = bid & 7;
    const int h  = (bid >> 3) & 7;
    const int b  = bid >> 6;
    const int l0 = lb * TL;

    // ---- stage keys as Ek = exp2(c*k) ----
    for (int i = tid; i < S * (E / 4); i += THREADS) {
        int s = i >> 3, e4 = i & 7;
        float4 t = reinterpret_cast<const float4*>(
            k + ((size_t)((b * S + s) * H + h)) * E)[e4];
        t.x = ex2f(TWO_LOG2E * t.x); t.y = ex2f(TWO_LOG2E * t.y);
        t.z = ex2f(TWO_LOG2E * t.z); t.w = ex2f(TWO_LOG2E * t.w);
        *reinterpret_cast<float4*>(ks + s * KS_STRIDE + e4 * 4) = t;
    }

    const int l   = tid >> 4;        // 0..63 local L row
    const int eh  = (tid >> 3) & 1;  // e-half: groups 4*eh .. 4*eh+3
    const int sof = tid & 7;

    // ---- per-thread constants (half the groups) ----
    u64   qp01[4], qp23[4];
    float v0c[3], v1c[3], v2c[3], v3c[3];  // local groups 0..2 as quad scalars
    u64   vp01s, vp23s;                    // local group 3 packed
    float vsumtot = 0.f;
    {
        const float4* qg = reinterpret_cast<const float4*>(
            q + ((size_t)((b * L + l0 + l) * H + h)) * E);
        const float4* vg = reinterpret_cast<const float4*>(vvec);
#pragma unroll
        for (int e4 = 0; e4 < 8; ++e4) {   // vsum over ALL groups
            float4 u = vg[e4];
            vsumtot += (u.x + u.y) + (u.z + u.w);
        }
#pragma unroll
        for (int i = 0; i < 4; ++i) {
            int g = 4 * eh + i;
            float4 t = qg[g];
            qp01[i] = pk(ex2f(t.x * TWO_LOG2E), ex2f(t.y * TWO_LOG2E));
            qp23[i] = pk(ex2f(t.z * TWO_LOG2E), ex2f(t.w * TWO_LOG2E));
            float4 u = vg[g];
            if (i < 3) {
                v0c[i] = u.x; v1c[i] = u.y; v2c[i] = u.z; v3c[i] = u.w;
            } else {
                vp01s = pk(u.x, u.y);
                vp23s = pk(u.z, u.w);
            }
        }
    }
    __syncthreads();

    const u64 ONES2 = pk(1.f, 1.f);

    // ---- phase 1 ----
    {
        const float* maskrow = mask + (size_t)(l0 + l) * S;
        const float* klrow   = klen + (size_t)b * S;
        const float baseL = vsumtot * LOG2E;
        float psum = 0.f;
        float* scrow = sc + l * SC_STRIDE;

#define QUAD(i, ACC) do {                                                    \
            ulonglong2 kk2 = kr[i];                                          \
            u64 A2 = fma2(qp01[i], kk2.x, ONES2);                            \
            u64 B2 = fma2(qp23[i], kk2.y, ONES2);                            \
            float A0, A1, B0, B1; upk(A2, A0, A1); upk(B2, B0, B1);          \
            float denA = A0 * A1, denB = B0 * B1;                            \
            float numA = fmaf(v0c[i], A1, v1c[i] * A0);                      \
            float numB = fmaf(v2c[i], B1, v3c[i] * B0);                      \
            float num = fmaf(numA, denB, numB * denA);                       \
            ACC = fmaf(num, rcpf(denA * denB), ACC);                         \
        } while (0)

#define SIMPLE(i, VP01, VP23) do {                                           \
            ulonglong2 kk2 = kr[i];                                          \
            u64 d01 = fma2(qp01[i], kk2.x, ONES2);                           \
            u64 d23 = fma2(qp23[i], kk2.y, ONES2);                           \
            float a0, a1, a2, a3; upk(d01, a0, a1); upk(d23, a2, a3);        \
            accV = fma2(VP01, pk(rcpf(a0), rcpf(a1)), accV);                 \
            accV = fma2(VP23, pk(rcpf(a2), rcpf(a3)), accV);                 \
        } while (0)

#define FINALIZE(J, PAR) do {                                                \
            float vlo, vhi; upk(accV, vlo, vhi);                             \
            float ah = (accP0 + accP1) + (vlo + vhi);                        \
            float a = ah + __shfl_xor_sync(0xffffffffu, ah, 8);              \
            if (eh == (PAR)) {                                               \
                int sg = 8 * (J) + sof;                                      \
                float mk = maskrow[sg] + klrow[sg];                          \
                float p = ex2f(fmaf(-2.f * LOG2E, a, fmaf(LOG2E, mk, baseL))); \
                psum += p;                                                   \
                scrow[sg] = p;                                               \
            }                                                                \
        } while (0)

#pragma unroll 1
        for (int jj = 0; jj < 32; ++jj) {
            {   // even j: 3 quads + 1 simple
                int j = 2 * jj;
                const ulonglong2* kr = reinterpret_cast<const ulonglong2*>(
                    ks + (8 * j + sof) * KS_STRIDE + 16 * eh);
                float accP0 = 0.f, accP1 = 0.f;
                u64 accV = pk(0.f, 0.f);
                QUAD(0, accP0); QUAD(1, accP1); QUAD(2, accP0);
                SIMPLE(3, vp01s, vp23s);
                FINALIZE(j, 0);
            }
            {   // odd j: 2 quads + 2 simple (group 2 packed on the fly)
                int j = 2 * jj + 1;
                const ulonglong2* kr = reinterpret_cast<const ulonglong2*>(
                    ks + (8 * j + sof) * KS_STRIDE + 16 * eh);
                float accP0 = 0.f, accP1 = 0.f;
                u64 accV = pk(0.f, 0.f);
                QUAD(0, accP0); QUAD(1, accP1);
                SIMPLE(2, pk(v0c[2], v1c[2]), pk(v2c[2], v3c[2]));
                SIMPLE(3, vp01s, vp23s);
                FINALIZE(j, 1);
            }
        }
#undef QUAD
#undef SIMPLE
#undef FINALIZE

        // reduce psum over 16-lane (eh,sof) group -> row sum
        psum += __shfl_xor_sync(0xffffffffu, psum, 1);
        psum += __shfl_xor_sync(0xffffffffu, psum, 2);
        psum += __shfl_xor_sync(0xffffffffu, psum, 4);
        psum += __shfl_xor_sync(0xffffffffu, psum, 8);
        if ((tid & 15) == 0) rsum[l] = rcpf(psum);
    }
    __syncthreads();

    // ---- phase 3: 2x8 register tile, 4 s-subgroups, packed FMA ----
    {
        const int sgrp = tid >> 8;           // 0..3: s%64 in [16*sgrp, 16*sgrp+16)
        const int tt   = tid & 255;
        const int rg   = tt >> 3;            // 0..31 -> rows 2rg, 2rg+1
        const int d8   = (tt & 7) * 8;       // d slice

        u64 acc0[4], acc1[4];
#pragma unroll
        for (int m = 0; m < 4; ++m) { acc0[m] = pk(0.f, 0.f); acc1[m] = pk(0.f, 0.f); }

        for (int c = 0; c < 8; ++c) {
            {   // stage 64 V rows: exactly one float4 per thread
                int ss = tid >> 4, d4 = tid & 15;
                float4 t = reinterpret_cast<const float4*>(
                    vals + ((size_t)((b * S + c * 64 + ss) * H + h)) * D)[d4];
                *reinterpret_cast<float4*>(vs + ss * VS_STRIDE + d4 * 4) = t;
            }
            __syncthreads();

            const float* Pb = sc + (2 * rg) * SC_STRIDE + c * 64 + 16 * sgrp;
            const float* Vb = vs + (16 * sgrp) * VS_STRIDE + d8;
#pragma unroll
            for (int jb = 0; jb < 4; ++jb) {
                float4 p0 = *reinterpret_cast<const float4*>(Pb + 4 * jb);
                float4 p1 = *reinterpret_cast<const float4*>(Pb + SC_STRIDE + 4 * jb);
                float p0a[4] = {p0.x, p0.y, p0.z, p0.w};
                float p1a[4] = {p1.x, p1.y, p1.z, p1.w};
#pragma unroll
                for (int u = 0; u < 4; ++u) {
                    const ulonglong2* vr =
                        reinterpret_cast<const ulonglong2*>(Vb + (4 * jb + u) * VS_STRIDE);
                    ulonglong2 va = vr[0];
                    ulonglong2 vb2 = vr[1];
                    u64 pp0 = pk(p0a[u], p0a[u]);
                    u64 pp1 = pk(p1a[u], p1a[u]);
                    acc0[0] = fma2(va.x,  pp0, acc0[0]);
                    acc0[1] = fma2(va.y,  pp0, acc0[1]);
                    acc0[2] = fma2(vb2.x, pp0, acc0[2]);
                    acc0[3] = fma2(vb2.y, pp0, acc0[3]);
                    acc1[0] = fma2(va.x,  pp1, acc1[0]);
                    acc1[1] = fma2(va.y,  pp1, acc1[1]);
                    acc1[2] = fma2(vb2.x, pp1, acc1[2]);
                    acc1[3] = fma2(vb2.y, pp1, acc1[3]);
                }
            }
            __syncthreads();
        }

        // partials into pbuf (overlaid on dead ks)
        float* pbuf = ks;  // [4][64][PB_STRIDE]
#pragma unroll
        for (int r = 0; r < 2; ++r) {
            const u64* acc = r ? acc1 : acc0;
            u64* dst = reinterpret_cast<u64*>(
                pbuf + (sgrp * 64 + 2 * rg + r) * PB_STRIDE + d8);
            reinterpret_cast<ulonglong2*>(dst)[0] = make_ulonglong2(acc[0], acc[1]);
            reinterpret_cast<ulonglong2*>(dst)[1] = make_ulonglong2(acc[2], acc[3]);
        }
        __syncthreads();

        // 4-way reduce + scale + store: thread -> (row, 4-d slice)
        {
            int row = tid >> 4;
            int c4  = (tid & 15) * 4;
            const float* p0 = pbuf + (0 * 64 + row) * PB_STRIDE + c4;
            const float* p1 = pbuf + (1 * 64 + row) * PB_STRIDE + c4;
            const float* p2 = pbuf + (2 * 64 + row) * PB_STRIDE + c4;
            const float* p3 = pbuf + (3 * 64 + row) * PB_STRIDE + c4;
            float r = rsum[row];
            float4 a0 = *reinterpret_cast<const float4*>(p0);
            float4 a1 = *reinterpret_cast<const float4*>(p1);
            float4 a2 = *reinterpret_cast<const float4*>(p2);
            float4 a3 = *reinterpret_cast<const float4*>(p3);
            float4 o;
            o.x = ((a0.x + a1.x) + (a2.x + a3.x)) * r;
            o.y = ((a0.y + a1.y) + (a2.y + a3.y)) * r;
            o.z = ((a0.z + a1.z) + (a2.z + a3.z)) * r;
            o.w = ((a0.w + a1.w) + (a2.w + a3.w)) * r;
            *reinterpret_cast<float4*>(
                out + ((size_t)((b * L + l0 + row) * H + h)) * D + c4) = o;
        }
    }
}

extern "C" void kernel_launch(void* const* d_in, const int* in_sizes, int n_in,
                              void* d_out, int out_size)
{
    (void)in_sizes; (void)n_in; (void)out_size;
    cudaFuncSetAttribute(addattn_kernel,
                         cudaFuncAttributeMaxDynamicSharedMemorySize, SMEM_BYTES);
    const float* q    = (const float*)d_in[0];
    const float* k    = (const float*)d_in[1];
    const float* vals = (const float*)d_in[2];
    const float* vvec = (const float*)d_in[3];
    const float* mask = (const float*)d_in[4];
    const float* klen = (const float*)d_in[5];
    addattn_kernel<<<B * H * (L / TL), THREADS, SMEM_BYTES>>>(
        q, k, vals, vvec, mask, klen, (float*)d_out);
}

// round 12
// speedup vs baseline: 1.4696x; 1.3872x over previous
#include <cuda_runtime.h>
#include <cstdint>

// AdditiveAttention: B=2, L=512, S=512, H=8, E=32, D=64 (fp32)
// Phase 1 (R6-proven): score via e^{2x}=e^{2q}*e^{2k}, quad-combine (1 rcp/4
// elems) + packed-simple; exp fused (scores bounded by sum|v|).
// Phase 3 NEW: V transposed in smem (s-major) -> P and V pack along s from
// LDS directly; fma2 with (even-s, odd-s) accumulators; zero pk MOVs.

namespace {
constexpr int B = 2, L = 512, S = 512, H = 8, E = 32, D = 64;
constexpr int TL = 64;
constexpr int THREADS = 512;
constexpr int SC_STRIDE = 524;    // %4==0 (LDS.128), row-pair quads distinct
constexpr int KS_STRIDE = 36;
constexpr int VT_STRIDE = 66;     // s-major V rows; 33*d % 16 distinct pairs
constexpr int PB_STRIDE = 68;
constexpr int SMEM_FLOATS = TL * SC_STRIDE + S * KS_STRIDE + D * VT_STRIDE + TL + S;
constexpr int SMEM_BYTES = SMEM_FLOATS * (int)sizeof(float);  // ~227.1KB
constexpr float TWO_LOG2E = 2.885390081777927f;
constexpr float LOG2E = 1.4426950408889634f;
}

using u64 = unsigned long long;

__device__ __forceinline__ float ex2f(float x) {
    float y; asm("ex2.approx.f32 %0, %1;" : "=f"(y) : "f"(x)); return y;
}
__device__ __forceinline__ float rcpf(float x) {
    float y; asm("rcp.approx.f32 %0, %1;" : "=f"(y) : "f"(x)); return y;
}
__device__ __forceinline__ u64 pk(float a, float b) {
    u64 d; asm("mov.b64 %0, {%1, %2};" : "=l"(d) : "f"(a), "f"(b)); return d;
}
__device__ __forceinline__ void upk(u64 d, float& a, float& b) {
    asm("mov.b64 {%0, %1}, %2;" : "=f"(a), "=f"(b) : "l"(d));
}
__device__ __forceinline__ u64 fma2(u64 a, u64 b, u64 c) {
    u64 d; asm("fma.rn.f32x2 %0, %1, %2, %3;" : "=l"(d) : "l"(a), "l"(b), "l"(c)); return d;
}

__global__ void __launch_bounds__(THREADS, 1)
addattn_kernel(const float* __restrict__ q, const float* __restrict__ k,
               const float* __restrict__ vals, const float* __restrict__ vvec,
               const float* __restrict__ mask, const float* __restrict__ klen,
               float* __restrict__ out)
{
    extern __shared__ float sm[];
    float* sc   = sm;                     // [TL][SC_STRIDE] unnormalized probs
    float* ks   = sc + TL * SC_STRIDE;    // [S][KS_STRIDE] Ek; reused as pbuf
    float* vsT  = ks + S * KS_STRIDE;     // [D][VT_STRIDE] transposed V chunk
    float* rsum = vsT + D * VT_STRIDE;    // [TL]
    float* klsm = rsum + TL;              // [S] staged klen row

    const int tid = threadIdx.x;
    const int bid = blockIdx.x;
    const int lb = bid & 7;
    const int h  = (bid >> 3) & 7;
    const int b  = bid >> 6;
    const int l0 = lb * TL;

    // ---- stage keys as Ek = exp2(c*k); stage klen row ----
    for (int i = tid; i < S * (E / 4); i += THREADS) {
        int s = i >> 3, e4 = i & 7;
        float4 t = reinterpret_cast<const float4*>(
            k + ((size_t)((b * S + s) * H + h)) * E)[e4];
        t.x = ex2f(TWO_LOG2E * t.x); t.y = ex2f(TWO_LOG2E * t.y);
        t.z = ex2f(TWO_LOG2E * t.z); t.w = ex2f(TWO_LOG2E * t.w);
        *reinterpret_cast<float4*>(ks + s * KS_STRIDE + e4 * 4) = t;
    }
    if (tid < S) klsm[tid] = klen[(size_t)b * S + tid];

    const int l   = tid >> 3;   // 0..63 local L row
    const int sof = tid & 7;

    // ---- per-thread constants ----
    u64   qp01[8], qp23[8];
    float v0c[5], v1c[5], v2c[5], v3c[5];
    u64   vp01s[3], vp23s[3];
    float vsumtot = 0.f;
    {
        const float4* qg = reinterpret_cast<const float4*>(
            q + ((size_t)((b * L + l0 + l) * H + h)) * E);
        const float4* vg = reinterpret_cast<const float4*>(vvec);
#pragma unroll
        for (int e4 = 0; e4 < 8; ++e4) {
            float4 t = qg[e4];
            qp01[e4] = pk(ex2f(t.x * TWO_LOG2E), ex2f(t.y * TWO_LOG2E));
            qp23[e4] = pk(ex2f(t.z * TWO_LOG2E), ex2f(t.w * TWO_LOG2E));
            float4 u = vg[e4];
            vsumtot += (u.x + u.y) + (u.z + u.w);
            if (e4 < 5) {
                v0c[e4] = u.x; v1c[e4] = u.y; v2c[e4] = u.z; v3c[e4] = u.w;
            } else {
                vp01s[e4 - 5] = pk(u.x, u.y);
                vp23s[e4 - 5] = pk(u.z, u.w);
            }
        }
    }
    __syncthreads();

    const u64 ONES2 = pk(1.f, 1.f);

    // ---- phase 1: p = exp(score) fused; per-thread row partial sum ----
    {
        const float* maskrow = mask + (size_t)(l0 + l) * S;
        const float baseL = vsumtot * LOG2E;
        float psum = 0.f;
#pragma unroll 2
        for (int j = 0; j < S / 8; ++j) {
            int s = 8 * j + sof;
            const ulonglong2* kr = reinterpret_cast<const ulonglong2*>(ks + s * KS_STRIDE);
            float accP0 = 0.f, accP1 = 0.f;
            u64 accV = pk(0.f, 0.f);
#pragma unroll
            for (int g = 0; g < 5; ++g) {      // quad groups: 1 rcp / 4 elems
                ulonglong2 kk2 = kr[g];
                u64 A2 = fma2(qp01[g], kk2.x, ONES2);
                u64 B2 = fma2(qp23[g], kk2.y, ONES2);
                float A0, A1, B0, B1; upk(A2, A0, A1); upk(B2, B0, B1);
                float denA = A0 * A1;
                float denB = B0 * B1;
                float numA = fmaf(v0c[g], A1, v1c[g] * A0);
                float numB = fmaf(v2c[g], B1, v3c[g] * B0);
                float num = fmaf(numA, denB, numB * denA);
                float den = denA * denB;
                if (g & 1) accP1 = fmaf(num, rcpf(den), accP1);
                else       accP0 = fmaf(num, rcpf(den), accP0);
            }
#pragma unroll
            for (int g = 5; g < 8; ++g) {      // packed-simple groups
                ulonglong2 kk2 = kr[g];
                u64 d01 = fma2(qp01[g], kk2.x, ONES2);
                u64 d23 = fma2(qp23[g], kk2.y, ONES2);
                float a0, a1, a2, a3; upk(d01, a0, a1); upk(d23, a2, a3);
                u64 r01 = pk(rcpf(a0), rcpf(a1));
                u64 r23 = pk(rcpf(a2), rcpf(a3));
                accV = fma2(vp01s[g - 5], r01, accV);
                accV = fma2(vp23s[g - 5], r23, accV);
            }
            float vlo, vhi; upk(accV, vlo, vhi);
            float a = (accP0 + accP1) + (vlo + vhi);
            float mk = maskrow[s] + klsm[s];
            float p = ex2f(fmaf(-2.f * LOG2E, a, fmaf(LOG2E, mk, baseL)));
            psum += p;
            sc[l * SC_STRIDE + s] = p;
        }
        psum += __shfl_xor_sync(0xffffffffu, psum, 1);
        psum += __shfl_xor_sync(0xffffffffu, psum, 2);
        psum += __shfl_xor_sync(0xffffffffu, psum, 4);
        if (sof == 0) rsum[l] = rcpf(psum);
    }
    __syncthreads();

    // ---- phase 3: transposed-V dot products, zero pk ----
    // thread (sgrp, rg, cgd): rows 4rg..+3, d = {cgd+16m}, s in [32*sgrp,+32)
    {
        const int sgrp = tid >> 8;           // 0..1
        const int tt   = tid & 255;
        const int rg   = tt >> 4;            // 0..15
        const int cgd  = tt & 15;            // 0..15

        u64 acc[4][4];                       // [row][m]: (even-s, odd-s) sums
#pragma unroll
        for (int i = 0; i < 4; ++i)
#pragma unroll
            for (int m = 0; m < 4; ++m) acc[i][m] = pk(0.f, 0.f);

        for (int c = 0; c < 8; ++c) {
            // stage 64x64 V chunk transposed: coalesced LDG, scatter STS
#pragma unroll
            for (int t = tid; t < 64 * 16; t += THREADS) {
                int ss = t >> 4, d4 = t & 15;
                float4 v = *reinterpret_cast<const float4*>(
                    vals + ((size_t)((b * S + c * 64 + ss) * H + h)) * D + 4 * d4);
                vsT[(4 * d4 + 0) * VT_STRIDE + ss] = v.x;
                vsT[(4 * d4 + 1) * VT_STRIDE + ss] = v.y;
                vsT[(4 * d4 + 2) * VT_STRIDE + ss] = v.z;
                vsT[(4 * d4 + 3) * VT_STRIDE + ss] = v.w;
            }
            __syncthreads();

            const float* Pb = sc + (4 * rg) * SC_STRIDE + c * 64 + 32 * sgrp;
            const float* Vb = vsT + cgd * VT_STRIDE + 32 * sgrp;
#pragma unroll
            for (int st4 = 0; st4 < 8; ++st4) {   // 8 x 4s = 32 s
                ulonglong2 P[4];
#pragma unroll
                for (int i = 0; i < 4; ++i)
                    P[i] = *reinterpret_cast<const ulonglong2*>(
                        Pb + i * SC_STRIDE + 4 * st4);
#pragma unroll
                for (int m = 0; m < 4; ++m) {
                    const float* vr = Vb + m * (16 * VT_STRIDE) + 4 * st4;
                    u64 va  = *reinterpret_cast<const u64*>(vr);
                    u64 vb2 = *reinterpret_cast<const u64*>(vr + 2);
#pragma unroll
                    for (int i = 0; i < 4; ++i) {
                        acc[i][m] = fma2(P[i].x, va,  acc[i][m]);
                        acc[i][m] = fma2(P[i].y, vb2, acc[i][m]);
                    }
                }
            }
            __syncthreads();
        }

        // hsum + partials into pbuf (overlaid on dead ks): [2][64][PB_STRIDE]
        float* pbuf = ks;
#pragma unroll
        for (int i = 0; i < 4; ++i) {
#pragma unroll
            for (int m = 0; m < 4; ++m) {
                float lo, hi; upk(acc[i][m], lo, hi);
                pbuf[(sgrp * 64 + 4 * rg + i) * PB_STRIDE + cgd + 16 * m] = lo + hi;
            }
        }
        __syncthreads();

        // 2-way reduce + scale + store: thread -> (row, 8-d slice)
        {
            int row = tid >> 3;
            int d8  = (tid & 7) * 8;
            const float* pa = pbuf + row * PB_STRIDE + d8;
            const float* pb2 = pbuf + (64 + row) * PB_STRIDE + d8;
            float r = rsum[row];
            float* og = out + ((size_t)((b * L + l0 + row) * H + h)) * D + d8;
#pragma unroll
            for (int half = 0; half < 2; ++half) {
                float4 x = *reinterpret_cast<const float4*>(pa + 4 * half);
                float4 y = *reinterpret_cast<const float4*>(pb2 + 4 * half);
                float4 o;
                o.x = (x.x + y.x) * r;
                o.y = (x.y + y.y) * r;
                o.z = (x.z + y.z) * r;
                o.w = (x.w + y.w) * r;
                *reinterpret_cast<float4*>(og + 4 * half) = o;
            }
        }
    }
}

extern "C" void kernel_launch(void* const* d_in, const int* in_sizes, int n_in,
                              void* d_out, int out_size)
{
    (void)in_sizes; (void)n_in; (void)out_size;
    cudaFuncSetAttribute(addattn_kernel,
                         cudaFuncAttributeMaxDynamicSharedMemorySize, SMEM_BYTES);
    const float* q    = (const float*)d_in[0];
    const float* k    = (const float*)d_in[1];
    const float* vals = (const float*)d_in[2];
    const float* vvec = (const float*)d_in[3];
    const float* mask = (const float*)d_in[4];
    const float* klen = (const float*)d_in[5];
    addattn_kernel<<<B * H * (L / TL), THREADS, SMEM_BYTES>>>(
        q, k, vals, vvec, mask, klen, (float*)d_out);
}

// round 14
// speedup vs baseline: 1.4962x; 1.0181x over previous
#include <cuda_runtime.h>
#include <cstdint>

// AdditiveAttention: B=2, L=512, S=512, H=8, E=32, D=64 (fp32)
// Phase 1: score via e^{2x}=e^{2q}*e^{2k}, quad-combine (1 rcp/4 elems) +
//          packed-simple; exp fused (scores bounded by sum|v|).
// Phase 3: transposed V (s-major) so P and V pack along s straight from LDS;
//          NEW: double-buffered V chunks (bufA = vsT slot, bufB in dead ks),
//          register-prefetched LDG, ONE barrier per chunk.

namespace {
constexpr int B = 2, L = 512, S = 512, H = 8, E = 32, D = 64;
constexpr int TL = 64;
constexpr int THREADS = 512;
constexpr int SC_STRIDE = 524;
constexpr int KS_STRIDE = 36;
constexpr int VT_STRIDE = 66;     // s-major V rows
constexpr int VT_FLOATS = D * VT_STRIDE;  // 4224
constexpr int PB_STRIDE = 68;
constexpr int SMEM_FLOATS = TL * SC_STRIDE + S * KS_STRIDE + VT_FLOATS + TL + S;
constexpr int SMEM_BYTES = SMEM_FLOATS * (int)sizeof(float);
constexpr float TWO_LOG2E = 2.885390081777927f;
constexpr float LOG2E = 1.4426950408889634f;
}

using u64 = unsigned long long;

__device__ __forceinline__ float ex2f(float x) {
    float y; asm("ex2.approx.f32 %0, %1;" : "=f"(y) : "f"(x)); return y;
}
__device__ __forceinline__ float rcpf(float x) {
    float y; asm("rcp.approx.f32 %0, %1;" : "=f"(y) : "f"(x)); return y;
}
__device__ __forceinline__ u64 pk(float a, float b) {
    u64 d; asm("mov.b64 %0, {%1, %2};" : "=l"(d) : "f"(a), "f"(b)); return d;
}
__device__ __forceinline__ void upk(u64 d, float& a, float& b) {
    asm("mov.b64 {%0, %1}, %2;" : "=f"(a), "=f"(b) : "l"(d));
}
__device__ __forceinline__ u64 fma2(u64 a, u64 b, u64 c) {
    u64 d; asm("fma.rn.f32x2 %0, %1, %2, %3;" : "=l"(d) : "l"(a), "l"(b), "l"(c)); return d;
}

__global__ void __launch_bounds__(THREADS, 1)
addattn_kernel(const float* __restrict__ q, const float* __restrict__ k,
               const float* __restrict__ vals, const float* __restrict__ vvec,
               const float* __restrict__ mask, const float* __restrict__ klen,
               float* __restrict__ out)
{
    extern __shared__ float sm[];
    float* sc   = sm;                     // [TL][SC_STRIDE] unnormalized probs
    float* ks   = sc + TL * SC_STRIDE;    // [S][KS_STRIDE] Ek; dead after ph1
    float* bufA = ks + S * KS_STRIDE;     // [D][VT_STRIDE] V chunk (even c)
    float* rsum = bufA + VT_FLOATS;       // [TL]
    float* klsm = rsum + TL;              // [S]
    float* bufB = ks;                     // [D][VT_STRIDE] V chunk (odd c)
    float* pbuf = ks + VT_FLOATS;         // [2][64][PB_STRIDE] partials

    const int tid = threadIdx.x;
    const int bid = blockIdx.x;
    const int lb = bid & 7;
    const int h  = (bid >> 3) & 7;
    const int b  = bid >> 6;
    const int l0 = lb * TL;

    // ---- stage keys as Ek = exp2(c*k); stage klen row ----
    for (int i = tid; i < S * (E / 4); i += THREADS) {
        int s = i >> 3, e4 = i & 7;
        float4 t = reinterpret_cast<const float4*>(
            k + ((size_t)((b * S + s) * H + h)) * E)[e4];
        t.x = ex2f(TWO_LOG2E * t.x); t.y = ex2f(TWO_LOG2E * t.y);
        t.z = ex2f(TWO_LOG2E * t.z); t.w = ex2f(TWO_LOG2E * t.w);
        *reinterpret_cast<float4*>(ks + s * KS_STRIDE + e4 * 4) = t;
    }
    if (tid < S) klsm[tid] = klen[(size_t)b * S + tid];

    const int l   = tid >> 3;
    const int sof = tid & 7;

    // ---- per-thread constants ----
    u64   qp01[8], qp23[8];
    float v0c[5], v1c[5], v2c[5], v3c[5];
    u64   vp01s[3], vp23s[3];
    float vsumtot = 0.f;
    {
        const float4* qg = reinterpret_cast<const float4*>(
            q + ((size_t)((b * L + l0 + l) * H + h)) * E);
        const float4* vg = reinterpret_cast<const float4*>(vvec);
#pragma unroll
        for (int e4 = 0; e4 < 8; ++e4) {
            float4 t = qg[e4];
            qp01[e4] = pk(ex2f(t.x * TWO_LOG2E), ex2f(t.y * TWO_LOG2E));
            qp23[e4] = pk(ex2f(t.z * TWO_LOG2E), ex2f(t.w * TWO_LOG2E));
            float4 u = vg[e4];
            vsumtot += (u.x + u.y) + (u.z + u.w);
            if (e4 < 5) {
                v0c[e4] = u.x; v1c[e4] = u.y; v2c[e4] = u.z; v3c[e4] = u.w;
            } else {
                vp01s[e4 - 5] = pk(u.x, u.y);
                vp23s[e4 - 5] = pk(u.z, u.w);
            }
        }
    }
    __syncthreads();

    const u64 ONES2 = pk(1.f, 1.f);

    // ---- phase 1: p = exp(score) fused; per-thread row partial sum ----
    {
        const float* maskrow = mask + (size_t)(l0 + l) * S;
        const float baseL = vsumtot * LOG2E;
        float psum = 0.f;
#pragma unroll 2
        for (int j = 0; j < S / 8; ++j) {
            int s = 8 * j + sof;
            const ulonglong2* kr = reinterpret_cast<const ulonglong2*>(ks + s * KS_STRIDE);
            float accP0 = 0.f, accP1 = 0.f;
            u64 accV0 = pk(0.f, 0.f), accV1 = pk(0.f, 0.f);
#pragma unroll
            for (int g = 0; g < 5; ++g) {      // quad groups: 1 rcp / 4 elems
                ulonglong2 kk2 = kr[g];
                u64 A2 = fma2(qp01[g], kk2.x, ONES2);
                u64 B2 = fma2(qp23[g], kk2.y, ONES2);
                float A0, A1, B0, B1; upk(A2, A0, A1); upk(B2, B0, B1);
                float denA = A0 * A1;
                float denB = B0 * B1;
                float numA = fmaf(v0c[g], A1, v1c[g] * A0);
                float numB = fmaf(v2c[g], B1, v3c[g] * B0);
                float num = fmaf(numA, denB, numB * denA);
                float den = denA * denB;
                if (g & 1) accP1 = fmaf(num, rcpf(den), accP1);
                else       accP0 = fmaf(num, rcpf(den), accP0);
            }
#pragma unroll
            for (int g = 5; g < 8; ++g) {      // packed-simple groups
                ulonglong2 kk2 = kr[g];
                u64 d01 = fma2(qp01[g], kk2.x, ONES2);
                u64 d23 = fma2(qp23[g], kk2.y, ONES2);
                float a0, a1, a2, a3; upk(d01, a0, a1); upk(d23, a2, a3);
                u64 r01 = pk(rcpf(a0), rcpf(a1));
                u64 r23 = pk(rcpf(a2), rcpf(a3));
                accV0 = fma2(vp01s[g - 5], r01, accV0);
                accV1 = fma2(vp23s[g - 5], r23, accV1);
            }
            float vlo0, vhi0, vlo1, vhi1;
            upk(accV0, vlo0, vhi0); upk(accV1, vlo1, vhi1);
            float a = (accP0 + accP1) + ((vlo0 + vhi0) + (vlo1 + vhi1));
            float mk = maskrow[s] + klsm[s];
            float p = ex2f(fmaf(-2.f * LOG2E, a, fmaf(LOG2E, mk, baseL)));
            psum += p;
            sc[l * SC_STRIDE + s] = p;
        }
        psum += __shfl_xor_sync(0xffffffffu, psum, 1);
        psum += __shfl_xor_sync(0xffffffffu, psum, 2);
        psum += __shfl_xor_sync(0xffffffffu, psum, 4);
        if (sof == 0) rsum[l] = rcpf(psum);
    }
    __syncthreads();

    // ---- phase 3: transposed-V dot products, double-buffered chunks ----
    {
        const int sgrp = tid >> 8;           // 0..1
        const int tt   = tid & 255;
        const int rg   = tt >> 4;            // 0..15
        const int cgd  = tt & 15;            // 0..15

        // thread's two staging slots (t0 = tid, t1 = tid+512 of 1024)
        const int ss0 = tid >> 4,          d40 = tid & 15;
        const int ss1 = (tid + 512) >> 4,  d41 = tid & 15;  // (tid+512)&15 == tid&15

        u64 acc[4][4];
#pragma unroll
        for (int i = 0; i < 4; ++i)
#pragma unroll
            for (int m = 0; m < 4; ++m) acc[i][m] = pk(0.f, 0.f);

        // stage chunk 0 into bufA
        {
            float4 v0 = *reinterpret_cast<const float4*>(
                vals + ((size_t)((b * S + ss0) * H + h)) * D + 4 * d40);
            float4 v1 = *reinterpret_cast<const float4*>(
                vals + ((size_t)((b * S + ss1) * H + h)) * D + 4 * d41);
            bufA[(4 * d40 + 0) * VT_STRIDE + ss0] = v0.x;
            bufA[(4 * d40 + 1) * VT_STRIDE + ss0] = v0.y;
            bufA[(4 * d40 + 2) * VT_STRIDE + ss0] = v0.z;
            bufA[(4 * d40 + 3) * VT_STRIDE + ss0] = v0.w;
            bufA[(4 * d41 + 0) * VT_STRIDE + ss1] = v1.x;
            bufA[(4 * d41 + 1) * VT_STRIDE + ss1] = v1.y;
            bufA[(4 * d41 + 2) * VT_STRIDE + ss1] = v1.z;
            bufA[(4 * d41 + 3) * VT_STRIDE + ss1] = v1.w;
        }
        __syncthreads();

#pragma unroll 1
        for (int c = 0; c < 8; ++c) {
            // prefetch chunk c+1 into registers (LDG overlaps compute below)
            float4 n0, n1;
            if (c < 7) {
                n0 = *reinterpret_cast<const float4*>(
                    vals + ((size_t)((b * S + (c + 1) * 64 + ss0) * H + h)) * D + 4 * d40);
                n1 = *reinterpret_cast<const float4*>(
                    vals + ((size_t)((b * S + (c + 1) * 64 + ss1) * H + h)) * D + 4 * d41);
            }

            const float* vcur = (c & 1) ? bufB : bufA;
            const float* Pb = sc + (4 * rg) * SC_STRIDE + c * 64 + 32 * sgrp;
            const float* Vb = vcur + cgd * VT_STRIDE + 32 * sgrp;
#pragma unroll
            for (int st4 = 0; st4 < 8; ++st4) {
                ulonglong2 P[4];
#pragma unroll
                for (int i = 0; i < 4; ++i)
                    P[i] = *reinterpret_cast<const ulonglong2*>(
                        Pb + i * SC_STRIDE + 4 * st4);
#pragma unroll
                for (int m = 0; m < 4; ++m) {
                    const float* vr = Vb + m * (16 * VT_STRIDE) + 4 * st4;
                    u64 va  = *reinterpret_cast<const u64*>(vr);
                    u64 vb2 = *reinterpret_cast<const u64*>(vr + 2);
#pragma unroll
                    for (int i = 0; i < 4; ++i) {
                        acc[i][m] = fma2(P[i].x, va,  acc[i][m]);
                        acc[i][m] = fma2(P[i].y, vb2, acc[i][m]);
                    }
                }
            }

            if (c < 7) {
                float* vnxt = ((c + 1) & 1) ? bufB : bufA;
                vnxt[(4 * d40 + 0) * VT_STRIDE + ss0] = n0.x;
                vnxt[(4 * d40 + 1) * VT_STRIDE + ss0] = n0.y;
                vnxt[(4 * d40 + 2) * VT_STRIDE + ss0] = n0.z;
                vnxt[(4 * d40 + 3) * VT_STRIDE + ss0] = n0.w;
                vnxt[(4 * d41 + 0) * VT_STRIDE + ss1] = n1.x;
                vnxt[(4 * d41 + 1) * VT_STRIDE + ss1] = n1.y;
                vnxt[(4 * d41 + 2) * VT_STRIDE + ss1] = n1.z;
                vnxt[(4 * d41 + 3) * VT_STRIDE + ss1] = n1.w;
            }
            __syncthreads();
        }

        // hsum + partials into pbuf [2][64][PB_STRIDE]
#pragma unroll
        for (int i = 0; i < 4; ++i) {
#pragma unroll
            for (int m = 0; m < 4; ++m) {
                float lo, hi; upk(acc[i][m], lo, hi);
                pbuf[(sgrp * 64 + 4 * rg + i) * PB_STRIDE + cgd + 16 * m] = lo + hi;
            }
        }
        __syncthreads();

        // 2-way reduce + scale + store
        {
            int row = tid >> 3;
            int d8  = (tid & 7) * 8;
            const float* pa  = pbuf + row * PB_STRIDE + d8;
            const float* pb2 = pbuf + (64 + row) * PB_STRIDE + d8;
            float r = rsum[row];
            float* og = out + ((size_t)((b * L + l0 + row) * H + h)) * D + d8;
#pragma unroll
            for (int half = 0; half < 2; ++half) {
                float4 x = *reinterpret_cast<const float4*>(pa + 4 * half);
                float4 y = *reinterpret_cast<const float4*>(pb2 + 4 * half);
                float4 o;
                o.x = (x.x + y.x) * r;
                o.y = (x.y + y.y) * r;
                o.z = (x.z + y.z) * r;
                o.w = (x.w + y.w) * r;
                *reinterpret_cast<float4*>(og + 4 * half) = o;
            }
        }
    }
}

extern "C" void kernel_launch(void* const* d_in, const int* in_sizes, int n_in,
                              void* d_out, int out_size)
{
    (void)in_sizes; (void)n_in; (void)out_size;
    cudaFuncSetAttribute(addattn_kernel,
                         cudaFuncAttributeMaxDynamicSharedMemorySize, SMEM_BYTES);
    const float* q    = (const float*)d_in[0];
    const float* k    = (const float*)d_in[1];
    const float* vals = (const float*)d_in[2];
    const float* vvec = (const float*)d_in[3];
    const float* mask = (const float*)d_in[4];
    const float* klen = (const float*)d_in[5];
    addattn_kernel<<<B * H * (L / TL), THREADS, SMEM_BYTES>>>(
        q, k, vals, vvec, mask, klen, (float*)d_out);
}